// round 2
// baseline (speedup 1.0000x reference)
#include <cuda_runtime.h>

#define NPTS 100000
#define CDIM 128
#define HDIM 64
#define NK   27
#define TILE 64
#define NTILES ((NPTS + TILE - 1) / TILE)   // 1563

// Scratch (allocation-free rule: __device__ globals)
__device__ float g_convx[NPTS * HDIM];
__device__ float g_trans[NPTS * HDIM];
__device__ float g_r1[NPTS * HDIM];
__device__ float g_r2[NPTS * HDIM];

using u64 = unsigned long long;

__device__ __forceinline__ u64 ffma2(u64 a, u64 b, u64 c) {
    u64 d;
    asm("fma.rn.f32x2 %0, %1, %2, %3;" : "=l"(d) : "l"(a), "l"(b), "l"(c));
    return d;
}
__device__ __forceinline__ u64 bcast2(float x) {
    u64 r;
    asm("mov.b64 %0, {%1, %1};" : "=l"(r) : "f"(x));
    return r;
}
__device__ __forceinline__ float2 unpack2(u64 v) {
    float2 f;
    asm("mov.b64 {%0, %1}, %2;" : "=f"(f.x), "=f"(f.y) : "l"(v));
    return f;
}

// ---------------------------------------------------------------------------
// K1: y = x @ w1 + b1 ; split into g_convx (cols 0..63) and g_trans (64..127)
// tile: 64 rows x 128 cols, 256 threads, thread = 4 rows x 8 cols (4 f32x2 pairs)
// ---------------------------------------------------------------------------
__global__ __launch_bounds__(256) void gemm1_kernel(const float* __restrict__ x,
                                                    const float* __restrict__ w1,
                                                    const float* __restrict__ b1)
{
    __shared__ float s_x[TILE][33];     // [row][kk]
    __shared__ float s_w[32][128];      // [kk][c]
    const int tid = threadIdx.x;
    const int p0  = blockIdx.x * TILE;
    const int rg  = tid >> 4;           // 0..15 -> rows rg*4..+3
    const int cg  = tid & 15;           // cols cg*8..+7

    u64 acc[4][4];
#pragma unroll
    for (int r = 0; r < 4; r++)
#pragma unroll
        for (int cp = 0; cp < 4; cp++) acc[r][cp] = 0ull;

    for (int k0 = 0; k0 < CDIM; k0 += 32) {
        __syncthreads();
        // load x tile (64 x 32), coalesced, row-major in smem
#pragma unroll
        for (int i = tid; i < TILE * 32; i += 256) {
            int r = i >> 5, kk = i & 31;
            int row = p0 + r;
            s_x[r][kk] = (row < NPTS) ? x[row * CDIM + k0 + kk] : 0.0f;
        }
        // load w chunk (32 x 128) as float4s
#pragma unroll
        for (int f = tid; f < 32 * 32; f += 256) {
            int kk = f >> 5, c4 = f & 31;
            *(float4*)&s_w[kk][c4 * 4] = *(const float4*)&w1[(k0 + kk) * CDIM + c4 * 4];
        }
        __syncthreads();
#pragma unroll
        for (int kk = 0; kk < 32; kk++) {
            const ulonglong2* wp = (const ulonglong2*)&s_w[kk][cg * 8];
            ulonglong2 wa = wp[0], wb = wp[1];
#pragma unroll
            for (int r = 0; r < 4; r++) {
                u64 g = bcast2(s_x[rg * 4 + r][kk]);
                acc[r][0] = ffma2(g, wa.x, acc[r][0]);
                acc[r][1] = ffma2(g, wa.y, acc[r][1]);
                acc[r][2] = ffma2(g, wb.x, acc[r][2]);
                acc[r][3] = ffma2(g, wb.y, acc[r][3]);
            }
        }
    }
#pragma unroll
    for (int r = 0; r < 4; r++) {
        int row = p0 + rg * 4 + r;
        if (row >= NPTS) continue;
#pragma unroll
        for (int cp = 0; cp < 4; cp++) {
            float2 v = unpack2(acc[r][cp]);
            int c = cg * 8 + cp * 2;
            float y0 = v.x + b1[c];
            float y1 = v.y + b1[c + 1];
            if (c < HDIM) {
                g_convx[row * HDIM + c]     = y0;
                g_convx[row * HDIM + c + 1] = y1;
            } else {
                g_trans[row * HDIM + c - HDIM]     = y0;
                g_trans[row * HDIM + c + 1 - HDIM] = y1;
            }
        }
    }
}

// ---------------------------------------------------------------------------
// K2/K3: sconv3 + ReLU. stage 0: g_convx -> g_r1 (rw1), stage 1: g_r1 -> g_r2
// Per tile of 64 points: for each of 27 offsets, gather G (64x64, stored
// transposed [c][p]) + stage W_k (64x64), accumulate C += G*W.
// 256 threads = 4 c-slices x (8 point-groups x 8 d-groups); thread = 8p x 8d.
// ---------------------------------------------------------------------------
__global__ __launch_bounds__(256) void sconv_kernel(const float* __restrict__ feat,
                                                    float* __restrict__ outp,
                                                    const float* __restrict__ rw,
                                                    const float* __restrict__ rb,
                                                    const int* __restrict__ nbr)
{
    __shared__ int   s_nbr[NK * TILE];
    __shared__ __align__(16) float s_g[64][68];   // [c][p] (also reused as [p][d] scratch)
    __shared__ __align__(16) float s_w[64][64];   // [c][d]

    const int tid   = threadIdx.x;
    const int p0    = blockIdx.x * TILE;
    const int slice = tid >> 6;          // c block of 16
    const int t6    = tid & 63;
    const int pg    = t6 >> 3;           // points pg*8..+7
    const int dg    = t6 & 7;            // cols  dg*8..+7

    for (int i = tid; i < NK * TILE; i += 256) {
        int k = i >> 6, p = i & 63;
        int pt = p0 + p;
        s_nbr[i] = (pt < NPTS) ? nbr[k * NPTS + pt] : -1;
    }

    u64 acc[8][4];
#pragma unroll
    for (int dd = 0; dd < 8; dd++)
#pragma unroll
        for (int pp = 0; pp < 4; pp++) acc[dd][pp] = 0ull;

    const int gp = tid >> 2;   // gather: point 0..63
    const int gq = tid & 3;    // gather: quarter

    for (int k = 0; k < NK; k++) {
        __syncthreads();
        // gather neighbor features (zeros if invalid), transposed into s_g[c][p]
        int idx = s_nbr[k * TILE + gp];
        const float4* src = (idx >= 0) ? (const float4*)&feat[(long)idx * HDIM] : nullptr;
#pragma unroll
        for (int j = 0; j < 4; j++) {
            int c0 = gq * 4 + j * 16;
            float4 v = src ? src[c0 >> 2] : make_float4(0.f, 0.f, 0.f, 0.f);
            s_g[c0 + 0][gp] = v.x;
            s_g[c0 + 1][gp] = v.y;
            s_g[c0 + 2][gp] = v.z;
            s_g[c0 + 3][gp] = v.w;
        }
        // stage W_k
        const float4* wsrc = (const float4*)&rw[k * HDIM * HDIM];
#pragma unroll
        for (int f = tid; f < 64 * 16; f += 256) {
            ((float4*)s_w)[f] = wsrc[f];
        }
        __syncthreads();
        // compute over this thread's c-slice
#pragma unroll
        for (int cc = 0; cc < 16; cc++) {
            int c = slice * 16 + cc;
            const ulonglong2* gpr = (const ulonglong2*)&s_g[c][pg * 8];
            ulonglong2 ga = gpr[0], gb = gpr[1];
            u64 gp01 = ga.x, gp23 = ga.y, gp45 = gb.x, gp67 = gb.y;
            float4 w4a = *(const float4*)&s_w[c][dg * 8];
            float4 w4b = *(const float4*)&s_w[c][dg * 8 + 4];
            u64 wv[8];
            wv[0] = bcast2(w4a.x); wv[1] = bcast2(w4a.y);
            wv[2] = bcast2(w4a.z); wv[3] = bcast2(w4a.w);
            wv[4] = bcast2(w4b.x); wv[5] = bcast2(w4b.y);
            wv[6] = bcast2(w4b.z); wv[7] = bcast2(w4b.w);
#pragma unroll
            for (int dd = 0; dd < 8; dd++) {
                acc[dd][0] = ffma2(wv[dd], gp01, acc[dd][0]);
                acc[dd][1] = ffma2(wv[dd], gp23, acc[dd][1]);
                acc[dd][2] = ffma2(wv[dd], gp45, acc[dd][2]);
                acc[dd][3] = ffma2(wv[dd], gp67, acc[dd][3]);
            }
        }
    }

    // reduce the 4 c-slices into s_g reused as [p][d]
    __syncthreads();
    for (int s = 0; s < 4; s++) {
        if (slice == s) {
#pragma unroll
            for (int dd = 0; dd < 8; dd++) {
                int d = dg * 8 + dd;
#pragma unroll
                for (int pp = 0; pp < 4; pp++) {
                    float2 v = unpack2(acc[dd][pp]);
                    int p = pg * 8 + pp * 2;
                    if (s == 0) {
                        s_g[p][d]     = v.x;
                        s_g[p + 1][d] = v.y;
                    } else {
                        s_g[p][d]     += v.x;
                        s_g[p + 1][d] += v.y;
                    }
                }
            }
        }
        __syncthreads();
    }

    // epilogue: bias + ReLU + store
    {
        int p  = tid >> 2;
        int pt = p0 + p;
        if (pt < NPTS) {
#pragma unroll
            for (int j = 0; j < 4; j++) {
                int c0 = (tid & 3) * 16 + j * 4;
                float4 r = *(const float4*)&s_g[p][c0];
                float4 o;
                o.x = fmaxf(r.x + rb[c0 + 0], 0.f);
                o.y = fmaxf(r.y + rb[c0 + 1], 0.f);
                o.z = fmaxf(r.z + rb[c0 + 2], 0.f);
                o.w = fmaxf(r.w + rb[c0 + 3], 0.f);
                *(float4*)&outp[(long)pt * HDIM + c0] = o;
            }
        }
    }
}

// ---------------------------------------------------------------------------
// K4: out = x + concat(g_r2 + 2*g_convx, g_trans) @ w2 + b2
// ---------------------------------------------------------------------------
__global__ __launch_bounds__(256) void gemm2_kernel(const float* __restrict__ x,
                                                    const float* __restrict__ w2,
                                                    const float* __restrict__ b2,
                                                    float* __restrict__ out)
{
    __shared__ float s_u[TILE][33];
    __shared__ float s_w[32][128];
    const int tid = threadIdx.x;
    const int p0  = blockIdx.x * TILE;
    const int rg  = tid >> 4;
    const int cg  = tid & 15;

    u64 acc[4][4];
#pragma unroll
    for (int r = 0; r < 4; r++)
#pragma unroll
        for (int cp = 0; cp < 4; cp++) acc[r][cp] = 0ull;

    for (int k0 = 0; k0 < CDIM; k0 += 32) {
        __syncthreads();
#pragma unroll
        for (int i = tid; i < TILE * 32; i += 256) {
            int r = i >> 5, kk = i & 31;
            int row = p0 + r;
            int j = k0 + kk;
            float v = 0.f;
            if (row < NPTS) {
                if (j < HDIM)
                    v = g_r2[row * HDIM + j] + 2.0f * g_convx[row * HDIM + j];
                else
                    v = g_trans[row * HDIM + j - HDIM];
            }
            s_u[r][kk] = v;
        }
#pragma unroll
        for (int f = tid; f < 32 * 32; f += 256) {
            int kk = f >> 5, c4 = f & 31;
            *(float4*)&s_w[kk][c4 * 4] = *(const float4*)&w2[(k0 + kk) * CDIM + c4 * 4];
        }
        __syncthreads();
#pragma unroll
        for (int kk = 0; kk < 32; kk++) {
            const ulonglong2* wp = (const ulonglong2*)&s_w[kk][cg * 8];
            ulonglong2 wa = wp[0], wb = wp[1];
#pragma unroll
            for (int r = 0; r < 4; r++) {
                u64 g = bcast2(s_u[rg * 4 + r][kk]);
                acc[r][0] = ffma2(g, wa.x, acc[r][0]);
                acc[r][1] = ffma2(g, wa.y, acc[r][1]);
                acc[r][2] = ffma2(g, wb.x, acc[r][2]);
                acc[r][3] = ffma2(g, wb.y, acc[r][3]);
            }
        }
    }
#pragma unroll
    for (int r = 0; r < 4; r++) {
        int row = p0 + rg * 4 + r;
        if (row >= NPTS) continue;
#pragma unroll
        for (int cp = 0; cp < 4; cp++) {
            float2 v = unpack2(acc[r][cp]);
            int c = cg * 8 + cp * 2;
            out[row * CDIM + c]     = v.x + b2[c]     + x[row * CDIM + c];
            out[row * CDIM + c + 1] = v.y + b2[c + 1] + x[row * CDIM + c + 1];
        }
    }
}

// ---------------------------------------------------------------------------
extern "C" void kernel_launch(void* const* d_in, const int* in_sizes, int n_in,
                              void* d_out, int out_size)
{
    const float* x   = (const float*)d_in[0];
    const float* w1  = (const float*)d_in[1];
    const float* b1  = (const float*)d_in[2];
    const float* w2  = (const float*)d_in[3];
    const float* b2  = (const float*)d_in[4];
    const float* rw1 = (const float*)d_in[5];
    const float* rb1 = (const float*)d_in[6];
    const float* rw2 = (const float*)d_in[7];
    const float* rb2 = (const float*)d_in[8];
    const int*   nbr = (const int*)d_in[9];
    float* out = (float*)d_out;

    float* p_convx; cudaGetSymbolAddress((void**)&p_convx, g_convx);
    float* p_trans; cudaGetSymbolAddress((void**)&p_trans, g_trans);
    float* p_r1;    cudaGetSymbolAddress((void**)&p_r1,    g_r1);
    float* p_r2;    cudaGetSymbolAddress((void**)&p_r2,    g_r2);

    gemm1_kernel<<<NTILES, 256>>>(x, w1, b1);
    sconv_kernel<<<NTILES, 256>>>(p_convx, p_r1, rw1, rb1, nbr);
    sconv_kernel<<<NTILES, 256>>>(p_r1,    p_r2, rw2, rb2, nbr);
    gemm2_kernel<<<NTILES, 256>>>(x, w2, b2, out);
}

// round 3
// speedup vs baseline: 1.6892x; 1.6892x over previous
#include <cuda_runtime.h>

#define NPTS 100000
#define CDIM 128
#define HDIM 64
#define NK   27
#define TILE 64
#define NTILES ((NPTS + TILE - 1) / TILE)   // 1563

// Scratch (allocation-free rule: __device__ globals)
__device__ float g_convx[NPTS * HDIM];
__device__ float g_trans[NPTS * HDIM];
__device__ float g_r1[NPTS * HDIM];
__device__ float g_r2[NPTS * HDIM];

using u64 = unsigned long long;

__device__ __forceinline__ u64 ffma2(u64 a, u64 b, u64 c) {
    u64 d;
    asm("fma.rn.f32x2 %0, %1, %2, %3;" : "=l"(d) : "l"(a), "l"(b), "l"(c));
    return d;
}
__device__ __forceinline__ u64 bcast2(float x) {
    u64 r;
    asm("mov.b64 %0, {%1, %1};" : "=l"(r) : "f"(x));
    return r;
}
__device__ __forceinline__ float2 unpack2(u64 v) {
    float2 f;
    asm("mov.b64 {%0, %1}, %2;" : "=f"(f.x), "=f"(f.y) : "l"(v));
    return f;
}

// ---------------------------------------------------------------------------
// Dynamic smem layouts
// ---------------------------------------------------------------------------
// sconv: nbr[27*64] | G[2][64][68] | W[2][64][64]
#define SC_NBR_OFF 0
#define SC_G_OFF   6912
#define SC_W_OFF   (SC_G_OFF + 2 * 64 * 68 * 4)       // 41728
#define SC_SMEM    (SC_W_OFF + 2 * 64 * 64 * 4)       // 74496

// gemm: X[64][132] | W[2][32][128]
#define GM_X_OFF 0
#define GM_W_OFF (64 * 132 * 4)                        // 33792
#define GM_SMEM  (GM_W_OFF + 2 * 32 * 128 * 4)        // 66560

// ---------------------------------------------------------------------------
// K1: y = x @ w1 + b1 ; split into g_convx (cols 0..63) and g_trans (64..127)
// Full x tile staged once; W chunks double-buffered with register prefetch.
// ---------------------------------------------------------------------------
__global__ __launch_bounds__(256) void gemm1_kernel(const float* __restrict__ x,
                                                    const float* __restrict__ w1,
                                                    const float* __restrict__ b1)
{
    extern __shared__ char sm[];
    float (*s_x)[132]      = (float(*)[132])(sm + GM_X_OFF);
    float (*s_w)[32][128]  = (float(*)[32][128])(sm + GM_W_OFF);

    const int tid = threadIdx.x;
    const int p0  = blockIdx.x * TILE;
    const int rg  = tid >> 4;           // rows rg*4..+3
    const int cg  = tid & 15;           // cols cg*8..+7

    // stage full x tile (64 x 128), vectorized
#pragma unroll
    for (int i = 0; i < 8; i++) {
        int f = tid + i * 256;
        int row = f >> 5, c4 = f & 31;
        int r = p0 + row;
        float4 v = (r < NPTS) ? *(const float4*)&x[r * CDIM + c4 * 4]
                              : make_float4(0.f, 0.f, 0.f, 0.f);
        *(float4*)&s_x[row][c4 * 4] = v;
    }
    // prefetch W chunk 0 into regs
    float4 wreg[4];
#pragma unroll
    for (int j = 0; j < 4; j++) wreg[j] = ((const float4*)w1)[tid + j * 256];

    u64 acc[4][4];
#pragma unroll
    for (int r = 0; r < 4; r++)
#pragma unroll
        for (int cp = 0; cp < 4; cp++) acc[r][cp] = 0ull;

    for (int ch = 0; ch < 4; ch++) {
        const int cur = ch & 1;
#pragma unroll
        for (int j = 0; j < 4; j++)
            ((float4*)s_w[cur])[tid + j * 256] = wreg[j];
        __syncthreads();
        if (ch < 3) {
            const float4* wsrc = (const float4*)&w1[(ch + 1) * 32 * CDIM];
#pragma unroll
            for (int j = 0; j < 4; j++) wreg[j] = wsrc[tid + j * 256];
        }
#pragma unroll
        for (int kk = 0; kk < 32; kk++) {
            const ulonglong2* wp = (const ulonglong2*)&s_w[cur][kk][cg * 8];
            ulonglong2 wa = wp[0], wb = wp[1];
#pragma unroll
            for (int r = 0; r < 4; r++) {
                u64 g = bcast2(s_x[rg * 4 + r][ch * 32 + kk]);
                acc[r][0] = ffma2(g, wa.x, acc[r][0]);
                acc[r][1] = ffma2(g, wa.y, acc[r][1]);
                acc[r][2] = ffma2(g, wb.x, acc[r][2]);
                acc[r][3] = ffma2(g, wb.y, acc[r][3]);
            }
        }
        __syncthreads();
    }
#pragma unroll
    for (int r = 0; r < 4; r++) {
        int row = p0 + rg * 4 + r;
        if (row >= NPTS) continue;
#pragma unroll
        for (int cp = 0; cp < 4; cp++) {
            float2 v = unpack2(acc[r][cp]);
            int c = cg * 8 + cp * 2;
            float2 o;
            o.x = v.x + b1[c];
            o.y = v.y + b1[c + 1];
            if (c < HDIM)
                *(float2*)&g_convx[row * HDIM + c] = o;
            else
                *(float2*)&g_trans[row * HDIM + c - HDIM] = o;
        }
    }
}

// ---------------------------------------------------------------------------
// K2/K3: sconv3 + ReLU. Double-buffered gather+weights, one barrier per k.
// 256 threads = 4 c-slices x (8 point-groups x 8 d-groups); thread = 8p x 8d.
// ---------------------------------------------------------------------------
__global__ __launch_bounds__(256, 2) void sconv_kernel(const float* __restrict__ feat,
                                                       float* __restrict__ outp,
                                                       const float* __restrict__ rw,
                                                       const float* __restrict__ rb,
                                                       const int* __restrict__ nbr)
{
    extern __shared__ char sm[];
    int*   s_nbr = (int*)(sm + SC_NBR_OFF);
    float (*s_g)[64][68] = (float(*)[64][68])(sm + SC_G_OFF);
    float (*s_w)[64][64] = (float(*)[64][64])(sm + SC_W_OFF);

    const int tid   = threadIdx.x;
    const int p0    = blockIdx.x * TILE;
    const int slice = tid >> 6;          // c block of 16
    const int t6    = tid & 63;
    const int pg    = t6 >> 3;           // points pg*8..+7
    const int dg    = t6 & 7;            // cols  dg*8..+7
    const int gp    = tid >> 2;          // gather: point 0..63
    const int gq    = tid & 3;           // gather: quarter

    for (int i = tid; i < NK * TILE; i += 256) {
        int k = i >> 6, p = i & 63;
        int pt = p0 + p;
        s_nbr[i] = (pt < NPTS) ? nbr[k * NPTS + pt] : -1;
    }
    __syncthreads();

    // prologue: load k=0 gather + weights into regs
    float4 gv[4], wv4[4];
    {
        int idx = s_nbr[gp];
        const float4* src = (idx >= 0) ? (const float4*)&feat[(long)idx * HDIM] : nullptr;
#pragma unroll
        for (int j = 0; j < 4; j++)
            gv[j] = src ? src[gq + 4 * j] : make_float4(0.f, 0.f, 0.f, 0.f);
        const float4* wsrc = (const float4*)rw;
#pragma unroll
        for (int j = 0; j < 4; j++) wv4[j] = wsrc[tid + j * 256];
    }

    u64 acc[8][4];
#pragma unroll
    for (int dd = 0; dd < 8; dd++)
#pragma unroll
        for (int pp = 0; pp < 4; pp++) acc[dd][pp] = 0ull;

    for (int k = 0; k < NK; k++) {
        const int cur = k & 1;
        // stage regs -> smem (transposed G)
#pragma unroll
        for (int j = 0; j < 4; j++) {
            int c0 = gq * 4 + j * 16;
            s_g[cur][c0 + 0][gp] = gv[j].x;
            s_g[cur][c0 + 1][gp] = gv[j].y;
            s_g[cur][c0 + 2][gp] = gv[j].z;
            s_g[cur][c0 + 3][gp] = gv[j].w;
        }
#pragma unroll
        for (int j = 0; j < 4; j++)
            ((float4*)s_w[cur])[tid + j * 256] = wv4[j];
        __syncthreads();

        // prefetch k+1 while computing k
        if (k < NK - 1) {
            int idx = s_nbr[(k + 1) * TILE + gp];
            const float4* src = (idx >= 0) ? (const float4*)&feat[(long)idx * HDIM] : nullptr;
#pragma unroll
            for (int j = 0; j < 4; j++)
                gv[j] = src ? src[gq + 4 * j] : make_float4(0.f, 0.f, 0.f, 0.f);
            const float4* wsrc = (const float4*)&rw[(k + 1) * HDIM * HDIM];
#pragma unroll
            for (int j = 0; j < 4; j++) wv4[j] = wsrc[tid + j * 256];
        }

        // compute this thread's c-slice
#pragma unroll
        for (int cc = 0; cc < 16; cc++) {
            int c = slice * 16 + cc;
            const ulonglong2* gpr = (const ulonglong2*)&s_g[cur][c][pg * 8];
            ulonglong2 ga = gpr[0], gb = gpr[1];
            u64 gp01 = ga.x, gp23 = ga.y, gp45 = gb.x, gp67 = gb.y;
            float4 w4a = *(const float4*)&s_w[cur][c][dg * 8];
            float4 w4b = *(const float4*)&s_w[cur][c][dg * 8 + 4];
            u64 wv[8];
            wv[0] = bcast2(w4a.x); wv[1] = bcast2(w4a.y);
            wv[2] = bcast2(w4a.z); wv[3] = bcast2(w4a.w);
            wv[4] = bcast2(w4b.x); wv[5] = bcast2(w4b.y);
            wv[6] = bcast2(w4b.z); wv[7] = bcast2(w4b.w);
#pragma unroll
            for (int dd = 0; dd < 8; dd++) {
                acc[dd][0] = ffma2(wv[dd], gp01, acc[dd][0]);
                acc[dd][1] = ffma2(wv[dd], gp23, acc[dd][1]);
                acc[dd][2] = ffma2(wv[dd], gp45, acc[dd][2]);
                acc[dd][3] = ffma2(wv[dd], gp67, acc[dd][3]);
            }
        }
    }

    // reduce 4 c-slices into s_g buffer 0 reused as [p][d]
    float (*s_o)[68] = (float(*)[68])(sm + SC_G_OFF);
    __syncthreads();
    for (int s = 0; s < 4; s++) {
        if (slice == s) {
#pragma unroll
            for (int dd = 0; dd < 8; dd++) {
                int d = dg * 8 + dd;
#pragma unroll
                for (int pp = 0; pp < 4; pp++) {
                    float2 v = unpack2(acc[dd][pp]);
                    int p = pg * 8 + pp * 2;
                    if (s == 0) {
                        s_o[p][d]     = v.x;
                        s_o[p + 1][d] = v.y;
                    } else {
                        s_o[p][d]     += v.x;
                        s_o[p + 1][d] += v.y;
                    }
                }
            }
        }
        __syncthreads();
    }

    // epilogue: bias + ReLU + store
    {
        int p  = tid >> 2;
        int pt = p0 + p;
        if (pt < NPTS) {
#pragma unroll
            for (int j = 0; j < 4; j++) {
                int c0 = (tid & 3) * 16 + j * 4;
                float4 r = *(const float4*)&s_o[p][c0];
                float4 o;
                o.x = fmaxf(r.x + rb[c0 + 0], 0.f);
                o.y = fmaxf(r.y + rb[c0 + 1], 0.f);
                o.z = fmaxf(r.z + rb[c0 + 2], 0.f);
                o.w = fmaxf(r.w + rb[c0 + 3], 0.f);
                *(float4*)&outp[(long)pt * HDIM + c0] = o;
            }
        }
    }
}

// ---------------------------------------------------------------------------
// K4: out = x + concat(g_r2 + 2*g_convx, g_trans) @ w2 + b2
// ---------------------------------------------------------------------------
__global__ __launch_bounds__(256) void gemm2_kernel(const float* __restrict__ x,
                                                    const float* __restrict__ w2,
                                                    const float* __restrict__ b2,
                                                    float* __restrict__ out)
{
    extern __shared__ char sm[];
    float (*s_u)[132]     = (float(*)[132])(sm + GM_X_OFF);
    float (*s_w)[32][128] = (float(*)[32][128])(sm + GM_W_OFF);

    const int tid = threadIdx.x;
    const int p0  = blockIdx.x * TILE;
    const int rg  = tid >> 4;
    const int cg  = tid & 15;

    // stage fused input tile (64 x 128): [r2 + 2*convx | trans]
#pragma unroll
    for (int i = 0; i < 8; i++) {
        int f = tid + i * 256;
        int row = f >> 5, q = f & 31;
        int r = p0 + row;
        float4 v = make_float4(0.f, 0.f, 0.f, 0.f);
        if (r < NPTS) {
            if (q < 16) {
                float4 a = *(const float4*)&g_r2[r * HDIM + q * 4];
                float4 b = *(const float4*)&g_convx[r * HDIM + q * 4];
                v = make_float4(fmaf(2.f, b.x, a.x), fmaf(2.f, b.y, a.y),
                                fmaf(2.f, b.z, a.z), fmaf(2.f, b.w, a.w));
            } else {
                v = *(const float4*)&g_trans[r * HDIM + (q - 16) * 4];
            }
        }
        *(float4*)&s_u[row][q * 4] = v;
    }
    float4 wreg[4];
#pragma unroll
    for (int j = 0; j < 4; j++) wreg[j] = ((const float4*)w2)[tid + j * 256];

    u64 acc[4][4];
#pragma unroll
    for (int r = 0; r < 4; r++)
#pragma unroll
        for (int cp = 0; cp < 4; cp++) acc[r][cp] = 0ull;

    for (int ch = 0; ch < 4; ch++) {
        const int cur = ch & 1;
#pragma unroll
        for (int j = 0; j < 4; j++)
            ((float4*)s_w[cur])[tid + j * 256] = wreg[j];
        __syncthreads();
        if (ch < 3) {
            const float4* wsrc = (const float4*)&w2[(ch + 1) * 32 * CDIM];
#pragma unroll
            for (int j = 0; j < 4; j++) wreg[j] = wsrc[tid + j * 256];
        }
#pragma unroll
        for (int kk = 0; kk < 32; kk++) {
            const ulonglong2* wp = (const ulonglong2*)&s_w[cur][kk][cg * 8];
            ulonglong2 wa = wp[0], wb = wp[1];
#pragma unroll
            for (int r = 0; r < 4; r++) {
                u64 g = bcast2(s_u[rg * 4 + r][ch * 32 + kk]);
                acc[r][0] = ffma2(g, wa.x, acc[r][0]);
                acc[r][1] = ffma2(g, wa.y, acc[r][1]);
                acc[r][2] = ffma2(g, wb.x, acc[r][2]);
                acc[r][3] = ffma2(g, wb.y, acc[r][3]);
            }
        }
        __syncthreads();
    }
#pragma unroll
    for (int r = 0; r < 4; r++) {
        int row = p0 + rg * 4 + r;
        if (row >= NPTS) continue;
#pragma unroll
        for (int cp = 0; cp < 4; cp++) {
            float2 v = unpack2(acc[r][cp]);
            int c = cg * 8 + cp * 2;
            float2 xv = *(const float2*)&x[row * CDIM + c];
            float2 o;
            o.x = v.x + b2[c]     + xv.x;
            o.y = v.y + b2[c + 1] + xv.y;
            *(float2*)&out[row * CDIM + c] = o;
        }
    }
}

// ---------------------------------------------------------------------------
extern "C" void kernel_launch(void* const* d_in, const int* in_sizes, int n_in,
                              void* d_out, int out_size)
{
    const float* x   = (const float*)d_in[0];
    const float* w1  = (const float*)d_in[1];
    const float* b1  = (const float*)d_in[2];
    const float* w2  = (const float*)d_in[3];
    const float* b2  = (const float*)d_in[4];
    const float* rw1 = (const float*)d_in[5];
    const float* rb1 = (const float*)d_in[6];
    const float* rw2 = (const float*)d_in[7];
    const float* rb2 = (const float*)d_in[8];
    const int*   nbr = (const int*)d_in[9];
    float* out = (float*)d_out;

    float* p_convx; cudaGetSymbolAddress((void**)&p_convx, g_convx);
    float* p_r1;    cudaGetSymbolAddress((void**)&p_r1,    g_r1);
    float* p_r2;    cudaGetSymbolAddress((void**)&p_r2,    g_r2);

    cudaFuncSetAttribute(gemm1_kernel, cudaFuncAttributeMaxDynamicSharedMemorySize, GM_SMEM);
    cudaFuncSetAttribute(sconv_kernel, cudaFuncAttributeMaxDynamicSharedMemorySize, SC_SMEM);
    cudaFuncSetAttribute(gemm2_kernel, cudaFuncAttributeMaxDynamicSharedMemorySize, GM_SMEM);

    gemm1_kernel<<<NTILES, 256, GM_SMEM>>>(x, w1, b1);
    sconv_kernel<<<NTILES, 256, SC_SMEM>>>(p_convx, p_r1, rw1, rb1, nbr);
    sconv_kernel<<<NTILES, 256, SC_SMEM>>>(p_r1,    p_r2, rw2, rb2, nbr);
    gemm2_kernel<<<NTILES, 256, GM_SMEM>>>(x, w2, b2, out);
}

// round 5
// speedup vs baseline: 2.1451x; 1.2699x over previous
#include <cuda_runtime.h>
#include <cstdint>

#define NPTS 100000
#define CDIM 128
#define HDIM 64
#define NK   27
#define TILE 64
#define NTILES ((NPTS + TILE - 1) / TILE)     // 1563 (gemm tiles)
#define TP    128
#define NT_MM ((NPTS + TP - 1) / TP)          // 782 (sconv mma tiles)

// Scratch (allocation-free rule: __device__ globals)
__device__ float g_convx[NPTS * HDIM];
__device__ float g_trans[NPTS * HDIM];
__device__ float g_r1[NPTS * HDIM];
__device__ float g_r2[NPTS * HDIM];

using u64 = unsigned long long;

__device__ __forceinline__ u64 ffma2(u64 a, u64 b, u64 c) {
    u64 d;
    asm("fma.rn.f32x2 %0, %1, %2, %3;" : "=l"(d) : "l"(a), "l"(b), "l"(c));
    return d;
}
__device__ __forceinline__ u64 bcast2(float x) {
    u64 r;
    asm("mov.b64 %0, {%1, %1};" : "=l"(r) : "f"(x));
    return r;
}
__device__ __forceinline__ float2 unpack2(u64 v) {
    float2 f;
    asm("mov.b64 {%0, %1}, %2;" : "=f"(f.x), "=f"(f.y) : "l"(v));
    return f;
}
__device__ __forceinline__ uint32_t tf32_rna(float x) {
    uint32_t r;
    asm("cvt.rna.tf32.f32 %0, %1;" : "=r"(r) : "f"(x));
    return r;
}
__device__ __forceinline__ uint4 tf32x4(float4 v) {
    uint4 o;
    o.x = tf32_rna(v.x); o.y = tf32_rna(v.y);
    o.z = tf32_rna(v.z); o.w = tf32_rna(v.w);
    return o;
}
__device__ __forceinline__ void mma_tf32(float* c, const uint32_t* a, const uint32_t* b) {
    asm volatile(
        "mma.sync.aligned.m16n8k8.row.col.f32.tf32.tf32.f32 "
        "{%0,%1,%2,%3}, {%4,%5,%6,%7}, {%8,%9}, {%0,%1,%2,%3};"
        : "+f"(c[0]), "+f"(c[1]), "+f"(c[2]), "+f"(c[3])
        : "r"(a[0]), "r"(a[1]), "r"(a[2]), "r"(a[3]), "r"(b[0]), "r"(b[1]));
}

// ---------------------------------------------------------------------------
// gemm dynamic smem: X[64][132] | W[2][32][128]
#define GM_X_OFF 0
#define GM_W_OFF (64 * 132 * 4)
#define GM_SMEM  (GM_W_OFF + 2 * 32 * 128 * 4)      // 66560

// sconv mma smem: nbr[27*128] | G[2][128][68] | W[2][64][72]
#define MM_NBR_OFF 0
#define MM_G_OFF   13824
#define MM_GSTR    68
#define MM_GBUF    (128 * MM_GSTR * 4)               // 34816
#define MM_W_OFF   (MM_G_OFF + 2 * MM_GBUF)          // 83456
#define MM_WSTR    72
#define MM_WBUF    (64 * MM_WSTR * 4)                // 18432
#define MM_SMEM    (MM_W_OFF + 2 * MM_WBUF)          // 120320

// ---------------------------------------------------------------------------
// K1: y = x @ w1 + b1 ; split into g_convx / g_trans  (unchanged from R3)
// ---------------------------------------------------------------------------
__global__ __launch_bounds__(256) void gemm1_kernel(const float* __restrict__ x,
                                                    const float* __restrict__ w1,
                                                    const float* __restrict__ b1)
{
    extern __shared__ char sm[];
    float (*s_x)[132]      = (float(*)[132])(sm + GM_X_OFF);
    float (*s_w)[32][128]  = (float(*)[32][128])(sm + GM_W_OFF);

    const int tid = threadIdx.x;
    const int p0  = blockIdx.x * TILE;
    const int rg  = tid >> 4;
    const int cg  = tid & 15;

#pragma unroll
    for (int i = 0; i < 8; i++) {
        int f = tid + i * 256;
        int row = f >> 5, c4 = f & 31;
        int r = p0 + row;
        float4 v = (r < NPTS) ? *(const float4*)&x[r * CDIM + c4 * 4]
                              : make_float4(0.f, 0.f, 0.f, 0.f);
        *(float4*)&s_x[row][c4 * 4] = v;
    }
    float4 wreg[4];
#pragma unroll
    for (int j = 0; j < 4; j++) wreg[j] = ((const float4*)w1)[tid + j * 256];

    u64 acc[4][4];
#pragma unroll
    for (int r = 0; r < 4; r++)
#pragma unroll
        for (int cp = 0; cp < 4; cp++) acc[r][cp] = 0ull;

    for (int ch = 0; ch < 4; ch++) {
        const int cur = ch & 1;
#pragma unroll
        for (int j = 0; j < 4; j++)
            ((float4*)s_w[cur])[tid + j * 256] = wreg[j];
        __syncthreads();
        if (ch < 3) {
            const float4* wsrc = (const float4*)&w1[(ch + 1) * 32 * CDIM];
#pragma unroll
            for (int j = 0; j < 4; j++) wreg[j] = wsrc[tid + j * 256];
        }
#pragma unroll
        for (int kk = 0; kk < 32; kk++) {
            const ulonglong2* wp = (const ulonglong2*)&s_w[cur][kk][cg * 8];
            ulonglong2 wa = wp[0], wb = wp[1];
#pragma unroll
            for (int r = 0; r < 4; r++) {
                u64 g = bcast2(s_x[rg * 4 + r][ch * 32 + kk]);
                acc[r][0] = ffma2(g, wa.x, acc[r][0]);
                acc[r][1] = ffma2(g, wa.y, acc[r][1]);
                acc[r][2] = ffma2(g, wb.x, acc[r][2]);
                acc[r][3] = ffma2(g, wb.y, acc[r][3]);
            }
        }
        __syncthreads();
    }
#pragma unroll
    for (int r = 0; r < 4; r++) {
        int row = p0 + rg * 4 + r;
        if (row >= NPTS) continue;
#pragma unroll
        for (int cp = 0; cp < 4; cp++) {
            float2 v = unpack2(acc[r][cp]);
            int c = cg * 8 + cp * 2;
            float2 o;
            o.x = v.x + b1[c];
            o.y = v.y + b1[c + 1];
            if (c < HDIM)
                *(float2*)&g_convx[row * HDIM + c] = o;
            else
                *(float2*)&g_trans[row * HDIM + c - HDIM] = o;
        }
    }
}

// ---------------------------------------------------------------------------
// sconv3 + ReLU via mma.sync tf32.
// CTA = 128 points, 8 warps in 4(m) x 2(n) grid; warp = 2 m-tiles x 4 n-tiles.
// G staged [p][c] (tf32 bits), W staged [c][d] (tf32 bits), double-buffered.
// ---------------------------------------------------------------------------
__global__ __launch_bounds__(256) void sconv_mma_kernel(const float* __restrict__ feat,
                                                        float* __restrict__ outp,
                                                        const float* __restrict__ rw,
                                                        const float* __restrict__ rb,
                                                        const int* __restrict__ nbr)
{
    extern __shared__ char sm[];
    int* s_nbr = (int*)(sm + MM_NBR_OFF);
    uint32_t* s_gb[2] = { (uint32_t*)(sm + MM_G_OFF), (uint32_t*)(sm + MM_G_OFF + MM_GBUF) };
    uint32_t* s_wb[2] = { (uint32_t*)(sm + MM_W_OFF), (uint32_t*)(sm + MM_W_OFF + MM_WBUF) };

    const int tid  = threadIdx.x;
    const int wid  = tid >> 5;
    const int lane = tid & 31;
    const int mw   = wid >> 1;     // 0..3 : point block of 32
    const int nw   = wid & 1;      // 0..1 : d block of 32
    const int g    = lane >> 2;    // group row 0..7
    const int tg   = lane & 3;     // thread-in-group
    const int p0   = blockIdx.x * TP;

    for (int i = tid; i < NK * TP; i += 256) {
        int k = i >> 7, p = i & 127;
        int pt = p0 + p;
        s_nbr[i] = (pt < NPTS) ? nbr[k * NPTS + pt] : -1;
    }
    __syncthreads();

    // gather role: 2 threads per point, each half (32 floats)
    const int pl = tid >> 1;
    const int hf = tid & 1;
    const int g_sts = pl * MM_GSTR + hf * 32;       // word offset

    // prologue: k=0
    uint4 gv[8]; uint4 wv[4];
    {
        int idx = s_nbr[pl];
        if (idx >= 0) {
            const float4* src = (const float4*)(feat + (long)idx * HDIM + hf * 32);
#pragma unroll
            for (int j = 0; j < 8; j++) gv[j] = tf32x4(src[j]);
        } else {
#pragma unroll
            for (int j = 0; j < 8; j++) gv[j] = make_uint4(0, 0, 0, 0);
        }
        const float4* ws = (const float4*)rw;
#pragma unroll
        for (int j = 0; j < 4; j++) wv[j] = tf32x4(ws[tid + j * 256]);
    }

    float acc[2][4][4];
#pragma unroll
    for (int mt = 0; mt < 2; mt++)
#pragma unroll
        for (int nt = 0; nt < 4; nt++)
#pragma unroll
            for (int i = 0; i < 4; i++) acc[mt][nt][i] = 0.f;

    for (int k = 0; k < NK; k++) {
        const int b = k & 1;
        // stage G (tf32 bits), [p][c]
        {
            uint32_t* gp = s_gb[b] + g_sts;
#pragma unroll
            for (int j = 0; j < 8; j++) *(uint4*)(gp + j * 4) = gv[j];
        }
        // stage W (tf32 bits), [c][d] stride 72
        {
#pragma unroll
            for (int j = 0; j < 4; j++) {
                int f = tid + j * 256;
                *(uint4*)(s_wb[b] + (f >> 4) * MM_WSTR + (f & 15) * 4) = wv[j];
            }
        }
        __syncthreads();

        // prefetch k+1
        if (k < NK - 1) {
            int idx = s_nbr[(k + 1) * TP + pl];
            if (idx >= 0) {
                const float4* src = (const float4*)(feat + (long)idx * HDIM + hf * 32);
#pragma unroll
                for (int j = 0; j < 8; j++) gv[j] = tf32x4(src[j]);
            } else {
#pragma unroll
                for (int j = 0; j < 8; j++) gv[j] = make_uint4(0, 0, 0, 0);
            }
            const float4* ws = (const float4*)(rw + (k + 1) * HDIM * HDIM);
#pragma unroll
            for (int j = 0; j < 4; j++) wv[j] = tf32x4(ws[tid + j * 256]);
        }

        // compute: 8 K-steps of m16n8k8
        const uint32_t* ga = s_gb[b] + (mw * 32 + g) * MM_GSTR + tg;
        const uint32_t* wb = s_wb[b] + tg * MM_WSTR + nw * 32 + g;
#pragma unroll
        for (int kk = 0; kk < 8; kk++) {
            const int co = kk * 8;
            uint32_t a[2][4];
#pragma unroll
            for (int mt = 0; mt < 2; mt++) {
                const uint32_t* gr = ga + mt * 16 * MM_GSTR + co;
                a[mt][0] = gr[0];
                a[mt][1] = gr[8 * MM_GSTR];
                a[mt][2] = gr[4];
                a[mt][3] = gr[8 * MM_GSTR + 4];
            }
            uint32_t bf[4][2];
#pragma unroll
            for (int nt = 0; nt < 4; nt++) {
                const uint32_t* wr = wb + co * MM_WSTR + nt * 8;
                bf[nt][0] = wr[0];
                bf[nt][1] = wr[4 * MM_WSTR];
            }
#pragma unroll
            for (int mt = 0; mt < 2; mt++)
#pragma unroll
                for (int nt = 0; nt < 4; nt++)
                    mma_tf32(acc[mt][nt], a[mt], bf[nt]);
        }
    }

    // epilogue: bias + ReLU + store (each thread owns 2 cols x 4 rows per tile pair)
#pragma unroll
    for (int mt = 0; mt < 2; mt++) {
#pragma unroll
        for (int half = 0; half < 2; half++) {
            int pt = p0 + mw * 32 + mt * 16 + g + half * 8;
            if (pt < NPTS) {
                float* orow = outp + (long)pt * HDIM;
#pragma unroll
                for (int nt = 0; nt < 4; nt++) {
                    int d = nw * 32 + nt * 8 + 2 * tg;
                    float2 bb = *(const float2*)&rb[d];
                    float2 o;
                    o.x = fmaxf(acc[mt][nt][half * 2 + 0] + bb.x, 0.f);
                    o.y = fmaxf(acc[mt][nt][half * 2 + 1] + bb.y, 0.f);
                    *(float2*)&orow[d] = o;
                }
            }
        }
    }
}

// ---------------------------------------------------------------------------
// K4: out = x + concat(g_r2 + 2*g_convx, g_trans) @ w2 + b2  (unchanged)
// ---------------------------------------------------------------------------
__global__ __launch_bounds__(256) void gemm2_kernel(const float* __restrict__ x,
                                                    const float* __restrict__ w2,
                                                    const float* __restrict__ b2,
                                                    float* __restrict__ out)
{
    extern __shared__ char sm[];
    float (*s_u)[132]     = (float(*)[132])(sm + GM_X_OFF);
    float (*s_w)[32][128] = (float(*)[32][128])(sm + GM_W_OFF);

    const int tid = threadIdx.x;
    const int p0  = blockIdx.x * TILE;
    const int rg  = tid >> 4;
    const int cg  = tid & 15;

#pragma unroll
    for (int i = 0; i < 8; i++) {
        int f = tid + i * 256;
        int row = f >> 5, q = f & 31;
        int r = p0 + row;
        float4 v = make_float4(0.f, 0.f, 0.f, 0.f);
        if (r < NPTS) {
            if (q < 16) {
                float4 a = *(const float4*)&g_r2[r * HDIM + q * 4];
                float4 b = *(const float4*)&g_convx[r * HDIM + q * 4];
                v = make_float4(fmaf(2.f, b.x, a.x), fmaf(2.f, b.y, a.y),
                                fmaf(2.f, b.z, a.z), fmaf(2.f, b.w, a.w));
            } else {
                v = *(const float4*)&g_trans[r * HDIM + (q - 16) * 4];
            }
        }
        *(float4*)&s_u[row][q * 4] = v;
    }
    float4 wreg[4];
#pragma unroll
    for (int j = 0; j < 4; j++) wreg[j] = ((const float4*)w2)[tid + j * 256];

    u64 acc[4][4];
#pragma unroll
    for (int r = 0; r < 4; r++)
#pragma unroll
        for (int cp = 0; cp < 4; cp++) acc[r][cp] = 0ull;

    for (int ch = 0; ch < 4; ch++) {
        const int cur = ch & 1;
#pragma unroll
        for (int j = 0; j < 4; j++)
            ((float4*)s_w[cur])[tid + j * 256] = wreg[j];
        __syncthreads();
        if (ch < 3) {
            const float4* wsrc = (const float4*)&w2[(ch + 1) * 32 * CDIM];
#pragma unroll
            for (int j = 0; j < 4; j++) wreg[j] = wsrc[tid + j * 256];
        }
#pragma unroll
        for (int kk = 0; kk < 32; kk++) {
            const ulonglong2* wp = (const ulonglong2*)&s_w[cur][kk][cg * 8];
            ulonglong2 wa = wp[0], wb = wp[1];
#pragma unroll
            for (int r = 0; r < 4; r++) {
                u64 g = bcast2(s_u[rg * 4 + r][ch * 32 + kk]);
                acc[r][0] = ffma2(g, wa.x, acc[r][0]);
                acc[r][1] = ffma2(g, wa.y, acc[r][1]);
                acc[r][2] = ffma2(g, wb.x, acc[r][2]);
                acc[r][3] = ffma2(g, wb.y, acc[r][3]);
            }
        }
        __syncthreads();
    }
#pragma unroll
    for (int r = 0; r < 4; r++) {
        int row = p0 + rg * 4 + r;
        if (row >= NPTS) continue;
#pragma unroll
        for (int cp = 0; cp < 4; cp++) {
            float2 v = unpack2(acc[r][cp]);
            int c = cg * 8 + cp * 2;
            float2 xv = *(const float2*)&x[row * CDIM + c];
            float2 o;
            o.x = v.x + b2[c]     + xv.x;
            o.y = v.y + b2[c + 1] + xv.y;
            *(float2*)&out[row * CDIM + c] = o;
        }
    }
}

// ---------------------------------------------------------------------------
extern "C" void kernel_launch(void* const* d_in, const int* in_sizes, int n_in,
                              void* d_out, int out_size)
{
    const float* x   = (const float*)d_in[0];
    const float* w1  = (const float*)d_in[1];
    const float* b1  = (const float*)d_in[2];
    const float* w2  = (const float*)d_in[3];
    const float* b2  = (const float*)d_in[4];
    const float* rw1 = (const float*)d_in[5];
    const float* rb1 = (const float*)d_in[6];
    const float* rw2 = (const float*)d_in[7];
    const float* rb2 = (const float*)d_in[8];
    const int*   nbr = (const int*)d_in[9];
    float* out = (float*)d_out;

    float* p_convx; cudaGetSymbolAddress((void**)&p_convx, g_convx);
    float* p_r1;    cudaGetSymbolAddress((void**)&p_r1,    g_r1);
    float* p_r2;    cudaGetSymbolAddress((void**)&p_r2,    g_r2);

    cudaFuncSetAttribute(gemm1_kernel,     cudaFuncAttributeMaxDynamicSharedMemorySize, GM_SMEM);
    cudaFuncSetAttribute(sconv_mma_kernel, cudaFuncAttributeMaxDynamicSharedMemorySize, MM_SMEM);
    cudaFuncSetAttribute(gemm2_kernel,     cudaFuncAttributeMaxDynamicSharedMemorySize, GM_SMEM);

    gemm1_kernel<<<NTILES, 256, GM_SMEM>>>(x, w1, b1);
    sconv_mma_kernel<<<NT_MM, 256, MM_SMEM>>>(p_convx, p_r1, rw1, rb1, nbr);
    sconv_mma_kernel<<<NT_MM, 256, MM_SMEM>>>(p_r1,    p_r2, rw2, rb2, nbr);
    gemm2_kernel<<<NTILES, 256, GM_SMEM>>>(x, w2, b2, out);
}

// round 6
// speedup vs baseline: 3.1885x; 1.4864x over previous
#include <cuda_runtime.h>
#include <cstdint>

#define NPTS 100000
#define CDIM 128
#define HDIM 64
#define NK   27
#define GP   128
#define NT_GM ((NPTS + GP - 1) / GP)          // 782 (gemm tiles)
#define TP    128
#define NT_MM ((NPTS + TP - 1) / TP)          // 782 (sconv tiles)

// Scratch (allocation-free rule: __device__ globals)
__device__ float g_convx[NPTS * HDIM];
__device__ float g_trans[NPTS * HDIM];
__device__ float g_r1[NPTS * HDIM];
__device__ float g_r2[NPTS * HDIM];

__device__ __forceinline__ uint32_t tf32_rna(float x) {
    uint32_t r;
    asm("cvt.rna.tf32.f32 %0, %1;" : "=r"(r) : "f"(x));
    return r;
}
__device__ __forceinline__ uint4 tf32x4(float4 v) {
    uint4 o;
    o.x = tf32_rna(v.x); o.y = tf32_rna(v.y);
    o.z = tf32_rna(v.z); o.w = tf32_rna(v.w);
    return o;
}
__device__ __forceinline__ void mma_tf32(float* c, const uint32_t* a, const uint32_t* b) {
    asm volatile(
        "mma.sync.aligned.m16n8k8.row.col.f32.tf32.tf32.f32 "
        "{%0,%1,%2,%3}, {%4,%5,%6,%7}, {%8,%9}, {%0,%1,%2,%3};"
        : "+f"(c[0]), "+f"(c[1]), "+f"(c[2]), "+f"(c[3])
        : "r"(a[0]), "r"(a[1]), "r"(a[2]), "r"(a[3]), "r"(b[0]), "r"(b[1]));
}

// ---------------------------------------------------------------------------
// gemm mma smem: X[128][132] | W[2][32][132]    (tf32 bit patterns)
#define GXSTR 132
#define GX_OFF 0
#define GW_OFF (GP * GXSTR * 4)                  // 67584
#define GWSTR 132
#define GW_BUF (32 * GWSTR * 4)                  // 16896
#define G_SMEM (GW_OFF + 2 * GW_BUF)             // 101376

// sconv mma smem: G[2][128][68] | W[2][64][72]  (no nbr table)
#define MM_GSTR 68
#define MM_GBUF (128 * MM_GSTR * 4)              // 34816
#define MM_G_OFF 0
#define MM_W_OFF (2 * MM_GBUF)                   // 69632
#define MM_WSTR 72
#define MM_WBUF (64 * MM_WSTR * 4)               // 18432
#define MM_SMEM (MM_W_OFF + 2 * MM_WBUF)         // 106496

// ---------------------------------------------------------------------------
// K1: y = x @ w1 + b1 ; split -> g_convx (d<64) / g_trans (d>=64).  tf32 mma.
// CTA = 128 rows x 128 cols; 8 warps 4m x 2n; warp = 2 mt x 8 nt.
// ---------------------------------------------------------------------------
__global__ __launch_bounds__(256, 2) void gemm1_kernel(const float* __restrict__ x,
                                                       const float* __restrict__ w1,
                                                       const float* __restrict__ b1)
{
    extern __shared__ char sm[];
    uint32_t* s_x = (uint32_t*)(sm + GX_OFF);
    uint32_t* s_wb[2] = { (uint32_t*)(sm + GW_OFF), (uint32_t*)(sm + GW_OFF + GW_BUF) };

    const int tid  = threadIdx.x;
    const int wid  = tid >> 5;
    const int lane = tid & 31;
    const int mw   = wid >> 1;
    const int nw   = wid & 1;
    const int g    = lane >> 2;
    const int tg   = lane & 3;
    const int p0   = blockIdx.x * GP;

    // stage X tile (128 x 128) as tf32
#pragma unroll
    for (int j = 0; j < 16; j++) {
        int f = tid + j * 256;
        int row = f >> 5, c4 = f & 31;
        int r = p0 + row;
        float4 v = (r < NPTS) ? *(const float4*)&x[r * CDIM + c4 * 4]
                              : make_float4(0.f, 0.f, 0.f, 0.f);
        *(uint4*)&s_x[row * GXSTR + c4 * 4] = tf32x4(v);
    }
    // prefetch W chunk 0
    uint4 wv[4];
#pragma unroll
    for (int j = 0; j < 4; j++) wv[j] = tf32x4(((const float4*)w1)[tid + j * 256]);

    float acc[2][8][4];
#pragma unroll
    for (int mt = 0; mt < 2; mt++)
#pragma unroll
        for (int nt = 0; nt < 8; nt++)
#pragma unroll
            for (int i = 0; i < 4; i++) acc[mt][nt][i] = 0.f;

    for (int ch = 0; ch < 4; ch++) {
        const int b = ch & 1;
#pragma unroll
        for (int j = 0; j < 4; j++) {
            int f = tid + j * 256;
            *(uint4*)&s_wb[b][(f >> 5) * GWSTR + (f & 31) * 4] = wv[j];
        }
        __syncthreads();
        if (ch < 3) {
            const float4* ws = (const float4*)&w1[(ch + 1) * 32 * CDIM];
#pragma unroll
            for (int j = 0; j < 4; j++) wv[j] = tf32x4(ws[tid + j * 256]);
        }
        const uint32_t* ga = s_x + (mw * 32 + g) * GXSTR + ch * 32 + tg;
        const uint32_t* wb = s_wb[b] + tg * GWSTR + nw * 64 + g;
#pragma unroll
        for (int kk = 0; kk < 4; kk++) {
            const int co = kk * 8;
            uint32_t a[2][4];
#pragma unroll
            for (int mt = 0; mt < 2; mt++) {
                const uint32_t* gr = ga + mt * 16 * GXSTR + co;
                a[mt][0] = gr[0];
                a[mt][1] = gr[8 * GXSTR];
                a[mt][2] = gr[4];
                a[mt][3] = gr[8 * GXSTR + 4];
            }
            uint32_t bf[8][2];
#pragma unroll
            for (int nt = 0; nt < 8; nt++) {
                const uint32_t* wr = wb + co * GWSTR + nt * 8;
                bf[nt][0] = wr[0];
                bf[nt][1] = wr[4 * GWSTR];
            }
#pragma unroll
            for (int mt = 0; mt < 2; mt++)
#pragma unroll
                for (int nt = 0; nt < 8; nt++)
                    mma_tf32(acc[mt][nt], a[mt], bf[nt]);
        }
    }

    // epilogue: + b1, split store
#pragma unroll
    for (int mt = 0; mt < 2; mt++) {
#pragma unroll
        for (int h = 0; h < 2; h++) {
            int row = p0 + mw * 32 + mt * 16 + g + h * 8;
            if (row < NPTS) {
#pragma unroll
                for (int nt = 0; nt < 8; nt++) {
                    int d = nw * 64 + nt * 8 + 2 * tg;
                    float2 bb = *(const float2*)&b1[d];
                    float2 o;
                    o.x = acc[mt][nt][h * 2 + 0] + bb.x;
                    o.y = acc[mt][nt][h * 2 + 1] + bb.y;
                    if (nw == 0)
                        *(float2*)&g_convx[row * HDIM + d] = o;
                    else
                        *(float2*)&g_trans[row * HDIM + d - HDIM] = o;
                }
            }
        }
    }
}

// ---------------------------------------------------------------------------
// K2/K3: sconv3 + ReLU via mma.sync tf32 (as R5), nbr loaded per-k (no table),
// smem 106.5KB -> 2 CTAs/SM.
// ---------------------------------------------------------------------------
__global__ __launch_bounds__(256, 2) void sconv_mma_kernel(const float* __restrict__ feat,
                                                           float* __restrict__ outp,
                                                           const float* __restrict__ rw,
                                                           const float* __restrict__ rb,
                                                           const int* __restrict__ nbr)
{
    extern __shared__ char sm[];
    uint32_t* s_gb[2] = { (uint32_t*)(sm + MM_G_OFF), (uint32_t*)(sm + MM_G_OFF + MM_GBUF) };
    uint32_t* s_wb[2] = { (uint32_t*)(sm + MM_W_OFF), (uint32_t*)(sm + MM_W_OFF + MM_WBUF) };

    const int tid  = threadIdx.x;
    const int wid  = tid >> 5;
    const int lane = tid & 31;
    const int mw   = wid >> 1;
    const int nw   = wid & 1;
    const int g    = lane >> 2;
    const int tg   = lane & 3;
    const int p0   = blockIdx.x * TP;

    // gather role: 2 threads per point, each half (32 floats)
    const int pl = tid >> 1;
    const int hf = tid & 1;
    const int pt_g = p0 + pl;
    const bool pt_ok = (pt_g < NPTS);
    const int g_sts = pl * MM_GSTR + hf * 32;

    // prologue: k=0
    uint4 gv[8]; uint4 wv[4];
    {
        int idx = pt_ok ? nbr[pt_g] : -1;
        if (idx >= 0) {
            const float4* src = (const float4*)(feat + (long)idx * HDIM + hf * 32);
#pragma unroll
            for (int j = 0; j < 8; j++) gv[j] = tf32x4(src[j]);
        } else {
#pragma unroll
            for (int j = 0; j < 8; j++) gv[j] = make_uint4(0, 0, 0, 0);
        }
        const float4* ws = (const float4*)rw;
#pragma unroll
        for (int j = 0; j < 4; j++) wv[j] = tf32x4(ws[tid + j * 256]);
    }

    float acc[2][4][4];
#pragma unroll
    for (int mt = 0; mt < 2; mt++)
#pragma unroll
        for (int nt = 0; nt < 4; nt++)
#pragma unroll
            for (int i = 0; i < 4; i++) acc[mt][nt][i] = 0.f;

    for (int k = 0; k < NK; k++) {
        const int b = k & 1;
        // stage G (tf32), [p][c]
        {
            uint32_t* gp = s_gb[b] + g_sts;
#pragma unroll
            for (int j = 0; j < 8; j++) *(uint4*)(gp + j * 4) = gv[j];
        }
        // stage W (tf32), [c][d] stride 72
        {
#pragma unroll
            for (int j = 0; j < 4; j++) {
                int f = tid + j * 256;
                *(uint4*)(s_wb[b] + (f >> 4) * MM_WSTR + (f & 15) * 4) = wv[j];
            }
        }
        __syncthreads();

        // prefetch k+1 (nbr idx -> feat row -> weights)
        if (k < NK - 1) {
            int idx = pt_ok ? nbr[(k + 1) * NPTS + pt_g] : -1;
            if (idx >= 0) {
                const float4* src = (const float4*)(feat + (long)idx * HDIM + hf * 32);
#pragma unroll
                for (int j = 0; j < 8; j++) gv[j] = tf32x4(src[j]);
            } else {
#pragma unroll
                for (int j = 0; j < 8; j++) gv[j] = make_uint4(0, 0, 0, 0);
            }
            const float4* ws = (const float4*)(rw + (k + 1) * HDIM * HDIM);
#pragma unroll
            for (int j = 0; j < 4; j++) wv[j] = tf32x4(ws[tid + j * 256]);
        }

        // compute: 8 K-steps of m16n8k8
        const uint32_t* ga = s_gb[b] + (mw * 32 + g) * MM_GSTR + tg;
        const uint32_t* wb = s_wb[b] + tg * MM_WSTR + nw * 32 + g;
#pragma unroll
        for (int kk = 0; kk < 8; kk++) {
            const int co = kk * 8;
            uint32_t a[2][4];
#pragma unroll
            for (int mt = 0; mt < 2; mt++) {
                const uint32_t* gr = ga + mt * 16 * MM_GSTR + co;
                a[mt][0] = gr[0];
                a[mt][1] = gr[8 * MM_GSTR];
                a[mt][2] = gr[4];
                a[mt][3] = gr[8 * MM_GSTR + 4];
            }
            uint32_t bf[4][2];
#pragma unroll
            for (int nt = 0; nt < 4; nt++) {
                const uint32_t* wr = wb + co * MM_WSTR + nt * 8;
                bf[nt][0] = wr[0];
                bf[nt][1] = wr[4 * MM_WSTR];
            }
#pragma unroll
            for (int mt = 0; mt < 2; mt++)
#pragma unroll
                for (int nt = 0; nt < 4; nt++)
                    mma_tf32(acc[mt][nt], a[mt], bf[nt]);
        }
    }

    // epilogue: bias + ReLU + store
#pragma unroll
    for (int mt = 0; mt < 2; mt++) {
#pragma unroll
        for (int half = 0; half < 2; half++) {
            int pt = p0 + mw * 32 + mt * 16 + g + half * 8;
            if (pt < NPTS) {
                float* orow = outp + (long)pt * HDIM;
#pragma unroll
                for (int nt = 0; nt < 4; nt++) {
                    int d = nw * 32 + nt * 8 + 2 * tg;
                    float2 bb = *(const float2*)&rb[d];
                    float2 o;
                    o.x = fmaxf(acc[mt][nt][half * 2 + 0] + bb.x, 0.f);
                    o.y = fmaxf(acc[mt][nt][half * 2 + 1] + bb.y, 0.f);
                    *(float2*)&orow[d] = o;
                }
            }
        }
    }
}

// ---------------------------------------------------------------------------
// K4: out = x + concat(g_r2 + 2*g_convx, g_trans) @ w2 + b2.  tf32 mma.
// ---------------------------------------------------------------------------
__global__ __launch_bounds__(256, 2) void gemm2_kernel(const float* __restrict__ x,
                                                       const float* __restrict__ w2,
                                                       const float* __restrict__ b2,
                                                       float* __restrict__ out)
{
    extern __shared__ char sm[];
    uint32_t* s_x = (uint32_t*)(sm + GX_OFF);
    uint32_t* s_wb[2] = { (uint32_t*)(sm + GW_OFF), (uint32_t*)(sm + GW_OFF + GW_BUF) };

    const int tid  = threadIdx.x;
    const int wid  = tid >> 5;
    const int lane = tid & 31;
    const int mw   = wid >> 1;
    const int nw   = wid & 1;
    const int g    = lane >> 2;
    const int tg   = lane & 3;
    const int p0   = blockIdx.x * GP;

    // stage fused input tile (128 x 128): [r2 + 2*convx | trans], tf32
#pragma unroll
    for (int j = 0; j < 16; j++) {
        int f = tid + j * 256;
        int row = f >> 5, c4 = f & 31;
        int r = p0 + row;
        float4 v = make_float4(0.f, 0.f, 0.f, 0.f);
        if (r < NPTS) {
            if (c4 < 16) {
                float4 a = *(const float4*)&g_r2[r * HDIM + c4 * 4];
                float4 b = *(const float4*)&g_convx[r * HDIM + c4 * 4];
                v = make_float4(fmaf(2.f, b.x, a.x), fmaf(2.f, b.y, a.y),
                                fmaf(2.f, b.z, a.z), fmaf(2.f, b.w, a.w));
            } else {
                v = *(const float4*)&g_trans[r * HDIM + (c4 - 16) * 4];
            }
        }
        *(uint4*)&s_x[row * GXSTR + c4 * 4] = tf32x4(v);
    }
    uint4 wv[4];
#pragma unroll
    for (int j = 0; j < 4; j++) wv[j] = tf32x4(((const float4*)w2)[tid + j * 256]);

    float acc[2][8][4];
#pragma unroll
    for (int mt = 0; mt < 2; mt++)
#pragma unroll
        for (int nt = 0; nt < 8; nt++)
#pragma unroll
            for (int i = 0; i < 4; i++) acc[mt][nt][i] = 0.f;

    for (int ch = 0; ch < 4; ch++) {
        const int b = ch & 1;
#pragma unroll
        for (int j = 0; j < 4; j++) {
            int f = tid + j * 256;
            *(uint4*)&s_wb[b][(f >> 5) * GWSTR + (f & 31) * 4] = wv[j];
        }
        __syncthreads();
        if (ch < 3) {
            const float4* ws = (const float4*)&w2[(ch + 1) * 32 * CDIM];
#pragma unroll
            for (int j = 0; j < 4; j++) wv[j] = tf32x4(ws[tid + j * 256]);
        }
        const uint32_t* ga = s_x + (mw * 32 + g) * GXSTR + ch * 32 + tg;
        const uint32_t* wb = s_wb[b] + tg * GWSTR + nw * 64 + g;
#pragma unroll
        for (int kk = 0; kk < 4; kk++) {
            const int co = kk * 8;
            uint32_t a[2][4];
#pragma unroll
            for (int mt = 0; mt < 2; mt++) {
                const uint32_t* gr = ga + mt * 16 * GXSTR + co;
                a[mt][0] = gr[0];
                a[mt][1] = gr[8 * GXSTR];
                a[mt][2] = gr[4];
                a[mt][3] = gr[8 * GXSTR + 4];
            }
            uint32_t bf[8][2];
#pragma unroll
            for (int nt = 0; nt < 8; nt++) {
                const uint32_t* wr = wb + co * GWSTR + nt * 8;
                bf[nt][0] = wr[0];
                bf[nt][1] = wr[4 * GWSTR];
            }
#pragma unroll
            for (int mt = 0; mt < 2; mt++)
#pragma unroll
                for (int nt = 0; nt < 8; nt++)
                    mma_tf32(acc[mt][nt], a[mt], bf[nt]);
        }
    }

    // epilogue: + b2 + x -> out
#pragma unroll
    for (int mt = 0; mt < 2; mt++) {
#pragma unroll
        for (int h = 0; h < 2; h++) {
            int row = p0 + mw * 32 + mt * 16 + g + h * 8;
            if (row < NPTS) {
#pragma unroll
                for (int nt = 0; nt < 8; nt++) {
                    int d = nw * 64 + nt * 8 + 2 * tg;
                    float2 bb = *(const float2*)&b2[d];
                    float2 xv = *(const float2*)&x[row * CDIM + d];
                    float2 o;
                    o.x = acc[mt][nt][h * 2 + 0] + bb.x + xv.x;
                    o.y = acc[mt][nt][h * 2 + 1] + bb.y + xv.y;
                    *(float2*)&out[row * CDIM + d] = o;
                }
            }
        }
    }
}

// ---------------------------------------------------------------------------
extern "C" void kernel_launch(void* const* d_in, const int* in_sizes, int n_in,
                              void* d_out, int out_size)
{
    const float* x   = (const float*)d_in[0];
    const float* w1  = (const float*)d_in[1];
    const float* b1  = (const float*)d_in[2];
    const float* w2  = (const float*)d_in[3];
    const float* b2  = (const float*)d_in[4];
    const float* rw1 = (const float*)d_in[5];
    const float* rb1 = (const float*)d_in[6];
    const float* rw2 = (const float*)d_in[7];
    const float* rb2 = (const float*)d_in[8];
    const int*   nbr = (const int*)d_in[9];
    float* out = (float*)d_out;

    float* p_convx; cudaGetSymbolAddress((void**)&p_convx, g_convx);
    float* p_r1;    cudaGetSymbolAddress((void**)&p_r1,    g_r1);
    float* p_r2;    cudaGetSymbolAddress((void**)&p_r2,    g_r2);

    cudaFuncSetAttribute(gemm1_kernel,     cudaFuncAttributeMaxDynamicSharedMemorySize, G_SMEM);
    cudaFuncSetAttribute(sconv_mma_kernel, cudaFuncAttributeMaxDynamicSharedMemorySize, MM_SMEM);
    cudaFuncSetAttribute(gemm2_kernel,     cudaFuncAttributeMaxDynamicSharedMemorySize, G_SMEM);

    gemm1_kernel<<<NT_GM, 256, G_SMEM>>>(x, w1, b1);
    sconv_mma_kernel<<<NT_MM, 256, MM_SMEM>>>(p_convx, p_r1, rw1, rb1, nbr);
    sconv_mma_kernel<<<NT_MM, 256, MM_SMEM>>>(p_r1,    p_r2, rw2, rb2, nbr);
    gemm2_kernel<<<NT_GM, 256, G_SMEM>>>(x, w2, b2, out);
}